// round 3
// baseline (speedup 1.0000x reference)
#include <cuda_runtime.h>
#include <cstdint>

#define TT   8
#define NN   20000
#define EE   640000
#define ETOT (EE + NN)   // edges + self loops
#define HID  32

// ---------------- static device scratch ----------------
__device__ int   g_count[NN];
__device__ int   g_off[NN + 1];
__device__ int   g_cursor[NN];
__device__ int   g_srclist[ETOT];
__device__ float g_h2[NN * HID];
__device__ float g_as2[NN];
__device__ float g_ad2[NN];
__device__ float g_h[NN * HID];     // GRU hidden state
__device__ float g_A1[4];           // As1[0..1], Ad1[0..1]

// ---------------- setup: zero state + fold layer-1 attention vectors ----------------
__global__ void k_setup(const float* __restrict__ W1,
                        const float* __restrict__ as1,
                        const float* __restrict__ ad1) {
    int i = blockIdx.x * blockDim.x + threadIdx.x;
    int stride = gridDim.x * blockDim.x;
    for (int j = i; j < NN * HID; j += stride) g_h[j] = 0.0f;
    for (int j = i; j < NN; j += stride) g_count[j] = 0;
    if (blockIdx.x == 0 && threadIdx.x < 4) {
        int h = threadIdx.x & 1;
        const float* a = (threadIdx.x >= 2) ? ad1 : as1;
        float s = 0.0f;
        for (int c = 0; c < HID; c++) s += W1[h * HID + c] * a[h * HID + c];
        g_A1[threadIdx.x] = s;
    }
}

// ---------------- CSR build ----------------
__global__ void k_count(const int* __restrict__ ei) {
    int i = blockIdx.x * blockDim.x + threadIdx.x;
    if (i >= ETOT) return;
    int dst = (i < EE) ? ei[EE + i] : (i - EE);
    atomicAdd(&g_count[dst], 1);
}

__global__ void k_scan() {
    __shared__ int partial[1024];
    const int CH = (NN + 1023) / 1024;   // 20
    int tid = threadIdx.x;
    int base = tid * CH;
    int s = 0;
    for (int j = 0; j < CH; j++) {
        int idx = base + j;
        if (idx < NN) s += g_count[idx];
    }
    partial[tid] = s;
    __syncthreads();
    for (int off = 1; off < 1024; off <<= 1) {
        int v = 0;
        if (tid >= off) v = partial[tid - off];
        __syncthreads();
        if (tid >= off) partial[tid] += v;
        __syncthreads();
    }
    int run = (tid == 0) ? 0 : partial[tid - 1];
    for (int j = 0; j < CH; j++) {
        int idx = base + j;
        if (idx < NN) {
            int c = g_count[idx];
            g_off[idx] = run;
            g_cursor[idx] = run;
            g_count[idx] = 0;     // ready for next timestep
            run += c;
        }
    }
    if (tid == 1023) g_off[NN] = partial[1023];
}

__global__ void k_scatter(const int* __restrict__ ei) {
    int i = blockIdx.x * blockDim.x + threadIdx.x;
    if (i >= ETOT) return;
    int src, dst;
    if (i < EE) { src = ei[i]; dst = ei[EE + i]; }
    else        { src = dst = i - EE; }
    int pos = atomicAdd(&g_cursor[dst], 1);
    g_srclist[pos] = src;
}

// ---------------- layer 1 (scalar attention) + projection to h2 / layer-2 logits ----------------
__global__ void k_layer1(const float* __restrict__ xt,
                         const float* __restrict__ W1,
                         const float* __restrict__ b1,
                         const float* __restrict__ W2,
                         const float* __restrict__ as2w,
                         const float* __restrict__ ad2w) {
    __shared__ float sW1[64], sB1[64], sW2[64 * 32], sAs2[32], sAd2[32];
    int tid = threadIdx.x;
    for (int j = tid; j < 64; j += blockDim.x) { sW1[j] = W1[j]; sB1[j] = b1[j]; }
    for (int j = tid; j < 2048; j += blockDim.x) sW2[j] = W2[j];
    for (int j = tid; j < 32; j += blockDim.x) { sAs2[j] = as2w[j]; sAd2[j] = ad2w[j]; }
    __syncthreads();

    int n = blockIdx.x * blockDim.x + tid;
    if (n >= NN) return;

    float As10 = g_A1[0], As11 = g_A1[1], Ad10 = g_A1[2], Ad11 = g_A1[3];
    float xd = xt[n];
    int beg = g_off[n], end = g_off[n + 1];

    float den0 = 0.f, den1 = 0.f, num0 = 0.f, num1 = 0.f;
    for (int e = beg; e < end; e++) {
        int s = g_srclist[e];
        float xs = __ldg(&xt[s]);
        float r0 = xs * As10 + xd * Ad10; r0 = (r0 > 0.f) ? r0 : 0.2f * r0;
        float w0 = __expf(r0); den0 += w0; num0 += w0 * xs;
        float r1 = xs * As11 + xd * Ad11; r1 = (r1 > 0.f) ? r1 : 0.2f * r1;
        float w1 = __expf(r1); den1 += w1; num1 += w1 * xs;
    }
    float S0 = num0 / (den0 + 1e-16f);
    float S1 = num1 / (den1 + 1e-16f);

    float z1[64];
#pragma unroll
    for (int k = 0; k < 64; k++) {
        float v = ((k < 32) ? S0 : S1) * sW1[k] + sB1[k];
        z1[k] = (v > 0.f) ? v : (__expf(v) - 1.0f);
    }

    float as2v = 0.f, ad2v = 0.f;
    float4* dst4 = (float4*)&g_h2[(size_t)n * HID];
    for (int c4 = 0; c4 < 8; c4++) {
        float a0 = 0.f, a1 = 0.f, a2 = 0.f, a3 = 0.f;
#pragma unroll
        for (int k = 0; k < 64; k++) {
            float z = z1[k];
            const float* w = &sW2[k * 32 + c4 * 4];
            a0 += z * w[0]; a1 += z * w[1]; a2 += z * w[2]; a3 += z * w[3];
        }
        int cb = c4 * 4;
        as2v += a0 * sAs2[cb] + a1 * sAs2[cb + 1] + a2 * sAs2[cb + 2] + a3 * sAs2[cb + 3];
        ad2v += a0 * sAd2[cb] + a1 * sAd2[cb + 1] + a2 * sAd2[cb + 2] + a3 * sAd2[cb + 3];
        dst4[c4] = make_float4(a0, a1, a2, a3);
    }
    g_as2[n] = as2v;
    g_ad2[n] = ad2v;
}

// ---------------- layer 2 gather (warp per dst node) + fused GRU cell ----------------
__global__ void k_layer2(const float* __restrict__ b2,
                         const float* __restrict__ Wih,
                         const float* __restrict__ Whh,
                         const float* __restrict__ bih,
                         const float* __restrict__ bhh) {
    __shared__ float sWih[96 * 33];
    __shared__ float sWhh[96 * 33];
    __shared__ float sbih[96], sbhh[96], sb2[32];
    int tid = threadIdx.x;
    for (int j = tid; j < 96 * 32; j += blockDim.x) {
        int r = j >> 5, k = j & 31;
        sWih[r * 33 + k] = Wih[j];
        sWhh[r * 33 + k] = Whh[j];
    }
    for (int j = tid; j < 96; j += blockDim.x) { sbih[j] = bih[j]; sbhh[j] = bhh[j]; }
    for (int j = tid; j < 32; j += blockDim.x) sb2[j] = b2[j];
    __syncthreads();

    int warp = tid >> 5, lane = tid & 31;
    int n = blockIdx.x * (blockDim.x >> 5) + warp;
    if (n >= NN) return;

    float ad2v = g_ad2[n];
    int beg = g_off[n], end = g_off[n + 1];
    float acc = 0.f, den = 0.f;
    for (int e = beg; e < end; e++) {
        int s = g_srclist[e];                 // warp-uniform broadcast load
        float raw = g_as2[s] + ad2v;
        raw = (raw > 0.f) ? raw : 0.2f * raw;
        float w = __expf(raw);
        den += w;
        acc += w * g_h2[(size_t)s * HID + lane];   // coalesced 128B row
    }
    float o = acc / (den + 1e-16f) + sb2[lane];
    float z2 = (o > 0.f) ? o : (__expf(o) - 1.0f);
    float hv = g_h[(size_t)n * HID + lane];

    float ri = 0.f, zi = 0.f, ni = 0.f, rh = 0.f, zh = 0.f, nh = 0.f;
#pragma unroll
    for (int k = 0; k < 32; k++) {
        float zk = __shfl_sync(0xffffffffu, z2, k);
        float hk = __shfl_sync(0xffffffffu, hv, k);
        ri += zk * sWih[lane * 33 + k];
        zi += zk * sWih[(32 + lane) * 33 + k];
        ni += zk * sWih[(64 + lane) * 33 + k];
        rh += hk * sWhh[lane * 33 + k];
        zh += hk * sWhh[(32 + lane) * 33 + k];
        nh += hk * sWhh[(64 + lane) * 33 + k];
    }
    float r = 1.0f / (1.0f + __expf(-(ri + sbih[lane] + rh + sbhh[lane])));
    float z = 1.0f / (1.0f + __expf(-(zi + sbih[32 + lane] + zh + sbhh[32 + lane])));
    float ng = tanhf(ni + sbih[64 + lane] + r * (nh + sbhh[64 + lane]));
    g_h[(size_t)n * HID + lane] = (1.0f - z) * ng + z * hv;
}

// ---------------- output projection ----------------
__global__ void k_out(const float* __restrict__ Wout,
                      const float* __restrict__ bout,
                      float* __restrict__ out) {
    int tid = threadIdx.x;
    int warp = tid >> 5, lane = tid & 31;
    int n = blockIdx.x * (blockDim.x >> 5) + warp;
    if (n >= NN) return;
    float v = g_h[(size_t)n * HID + lane] * __ldg(&Wout[lane]);
#pragma unroll
    for (int o = 16; o; o >>= 1) v += __shfl_xor_sync(0xffffffffu, v, o);
    if (lane == 0) out[n] = v + bout[0];
}

// ---------------- launcher ----------------
extern "C" void kernel_launch(void* const* d_in, const int* in_sizes, int n_in,
                              void* d_out, int out_size) {
    const float* x    = (const float*)d_in[0];
    const int*   ei   = (const int*)  d_in[1];
    const float* W1   = (const float*)d_in[2];
    const float* as1  = (const float*)d_in[3];
    const float* ad1  = (const float*)d_in[4];
    const float* b1   = (const float*)d_in[5];
    const float* W2   = (const float*)d_in[6];
    const float* as2  = (const float*)d_in[7];
    const float* ad2  = (const float*)d_in[8];
    const float* b2   = (const float*)d_in[9];
    const float* Wih  = (const float*)d_in[10];
    const float* Whh  = (const float*)d_in[11];
    const float* bih  = (const float*)d_in[12];
    const float* bhh  = (const float*)d_in[13];
    const float* Wout = (const float*)d_in[14];
    const float* bout = (const float*)d_in[15];
    float* out = (float*)d_out;

    const int EB = (ETOT + 255) / 256;

    k_setup<<<160, 256>>>(W1, as1, ad1);
    for (int t = 0; t < TT; t++) {
        const int*   eit = ei + (size_t)t * 2 * EE;
        const float* xt  = x  + (size_t)t * NN;
        k_count<<<EB, 256>>>(eit);
        k_scan<<<1, 1024>>>();
        k_scatter<<<EB, 256>>>(eit);
        k_layer1<<<(NN + 127) / 128, 128>>>(xt, W1, b1, W2, as2, ad2);
        k_layer2<<<(NN + 7) / 8, 256>>>(b2, Wih, Whh, bih, bhh);
    }
    k_out<<<(NN + 7) / 8, 256>>>(Wout, bout, out);
}

// round 4
// speedup vs baseline: 1.3115x; 1.3115x over previous
#include <cuda_runtime.h>
#include <cstdint>

#define TT   8
#define NN   20000
#define EE   640000
#define ETOT (EE + NN)   // edges + self loops
#define HID  32

// ---------------- static device scratch ----------------
__device__ int   g_count[TT * NN];
__device__ int   g_off[TT * (NN + 1)];
__device__ int   g_cursor[TT * NN];
__device__ int   g_srclist[TT * ETOT];
__device__ float g_h2[NN * HID];
__device__ float g_as2[NN];
__device__ float g_ad2[NN];
__device__ float g_h[NN * HID];     // GRU hidden state
__device__ float g_A1[4];           // As1[0..1], Ad1[0..1]

// ---------------- setup: zero state, counts=1 (self-loop), fold layer-1 attn ----------------
__global__ void k_setup(const float* __restrict__ W1,
                        const float* __restrict__ as1,
                        const float* __restrict__ ad1) {
    int i = blockIdx.x * blockDim.x + threadIdx.x;
    int stride = gridDim.x * blockDim.x;
    for (int j = i; j < NN * HID; j += stride) g_h[j] = 0.0f;
    for (int j = i; j < TT * NN; j += stride) g_count[j] = 1;   // self-loop pre-counted
    if (blockIdx.x == 0 && threadIdx.x < 4) {
        int h = threadIdx.x & 1;
        const float* a = (threadIdx.x >= 2) ? ad1 : as1;
        float s = 0.0f;
        for (int c = 0; c < HID; c++) s += W1[h * HID + c] * a[h * HID + c];
        g_A1[threadIdx.x] = s;
    }
}

// ---------------- batched CSR build (all 8 timesteps) ----------------
__global__ void k_count(const int* __restrict__ ei) {
    int t = blockIdx.y;
    int i = blockIdx.x * blockDim.x + threadIdx.x;
    if (i >= EE) return;
    int dst = ei[(size_t)t * 2 * EE + EE + i];
    atomicAdd(&g_count[t * NN + dst], 1);
}

__global__ void k_scan() {   // grid = TT blocks, 1024 threads
    __shared__ int partial[1024];
    const int CH = (NN + 1023) / 1024;   // 20
    int t = blockIdx.x;
    int tid = threadIdx.x;
    int base = tid * CH;
    const int cb = t * NN;
    int s = 0;
    for (int j = 0; j < CH; j++) {
        int idx = base + j;
        if (idx < NN) s += g_count[cb + idx];
    }
    partial[tid] = s;
    __syncthreads();
    for (int off = 1; off < 1024; off <<= 1) {
        int v = 0;
        if (tid >= off) v = partial[tid - off];
        __syncthreads();
        if (tid >= off) partial[tid] += v;
        __syncthreads();
    }
    int run = (tid == 0) ? 0 : partial[tid - 1];
    int* offp = g_off + t * (NN + 1);
    int* slp  = g_srclist + (size_t)t * ETOT;
    for (int j = 0; j < CH; j++) {
        int idx = base + j;
        if (idx < NN) {
            int c = g_count[cb + idx];
            offp[idx] = run;
            slp[run] = idx;                 // self-loop occupies first slot
            g_cursor[cb + idx] = run + 1;
            run += c;
        }
    }
    if (tid == 1023) offp[NN] = partial[1023];
}

__global__ void k_scatter(const int* __restrict__ ei) {
    int t = blockIdx.y;
    int i = blockIdx.x * blockDim.x + threadIdx.x;
    if (i >= EE) return;
    const size_t tb = (size_t)t * 2 * EE;
    int src = ei[tb + i];
    int dst = ei[tb + EE + i];
    int pos = atomicAdd(&g_cursor[t * NN + dst], 1);
    g_srclist[(size_t)t * ETOT + pos] = src;
}

// ---------------- layer 1: warp-per-node scalar attention + projection ----------------
__global__ void k_layer1(const float* __restrict__ xt,
                         const float* __restrict__ W1,
                         const float* __restrict__ b1,
                         const float* __restrict__ W2,
                         const float* __restrict__ as2w,
                         const float* __restrict__ ad2w,
                         int t) {
    __shared__ float sW1[64], sB1[64], sW2[64 * 32], sAs2[32], sAd2[32];
    int tid = threadIdx.x;
    for (int j = tid; j < 64; j += blockDim.x) { sW1[j] = W1[j]; sB1[j] = b1[j]; }
    for (int j = tid; j < 2048; j += blockDim.x) sW2[j] = W2[j];
    for (int j = tid; j < 32; j += blockDim.x) { sAs2[j] = as2w[j]; sAd2[j] = ad2w[j]; }
    __syncthreads();

    int warp = tid >> 5, lane = tid & 31;
    int n = blockIdx.x * 8 + warp;          // 2500 blocks * 8 warps = 20000 exactly

    float As10 = g_A1[0], As11 = g_A1[1], Ad10 = g_A1[2], Ad11 = g_A1[3];
    float xd = xt[n];
    const int* offp = g_off + t * (NN + 1);
    const int* slp  = g_srclist + (size_t)t * ETOT;
    int beg = offp[n], end = offp[n + 1];

    float den0 = 0.f, den1 = 0.f, num0 = 0.f, num1 = 0.f;
    for (int e = beg + lane; e < end; e += 32) {
        int s = slp[e];
        float xs = __ldg(&xt[s]);
        float r0 = xs * As10 + xd * Ad10; r0 = (r0 > 0.f) ? r0 : 0.2f * r0;
        float w0 = __expf(r0); den0 += w0; num0 += w0 * xs;
        float r1 = xs * As11 + xd * Ad11; r1 = (r1 > 0.f) ? r1 : 0.2f * r1;
        float w1 = __expf(r1); den1 += w1; num1 += w1 * xs;
    }
#pragma unroll
    for (int o = 16; o; o >>= 1) {
        den0 += __shfl_xor_sync(0xffffffffu, den0, o);
        num0 += __shfl_xor_sync(0xffffffffu, num0, o);
        den1 += __shfl_xor_sync(0xffffffffu, den1, o);
        num1 += __shfl_xor_sync(0xffffffffu, num1, o);
    }
    float S0 = num0 / (den0 + 1e-16f);
    float S1 = num1 / (den1 + 1e-16f);

    // per-lane z1 entries (lane, 32+lane)
    float v0 = S0 * sW1[lane] + sB1[lane];
    float z1a = (v0 > 0.f) ? v0 : (__expf(v0) - 1.0f);
    float v1 = S1 * sW1[32 + lane] + sB1[32 + lane];
    float z1b = (v1 > 0.f) ? v1 : (__expf(v1) - 1.0f);

    // output channel c = lane: a = sum_k z1[k] * W2[k][lane]
    float a = 0.f;
#pragma unroll
    for (int k = 0; k < 32; k++) {
        float zk = __shfl_sync(0xffffffffu, z1a, k);
        a += zk * sW2[k * 32 + lane];
    }
#pragma unroll
    for (int k = 0; k < 32; k++) {
        float zk = __shfl_sync(0xffffffffu, z1b, k);
        a += zk * sW2[(32 + k) * 32 + lane];
    }
    g_h2[(size_t)n * HID + lane] = a;

    float p = a * sAs2[lane];
    float q = a * sAd2[lane];
#pragma unroll
    for (int o = 16; o; o >>= 1) {
        p += __shfl_xor_sync(0xffffffffu, p, o);
        q += __shfl_xor_sync(0xffffffffu, q, o);
    }
    if (lane == 0) { g_as2[n] = p; g_ad2[n] = q; }
}

// ---------------- layer 2: 2 warps/node gather + fused GRU (+ fused output on last step) ----------------
__global__ void k_layer2(const float* __restrict__ b2,
                         const float* __restrict__ Wih,
                         const float* __restrict__ Whh,
                         const float* __restrict__ bih,
                         const float* __restrict__ bhh,
                         const float* __restrict__ Wout,
                         const float* __restrict__ bout,
                         float* __restrict__ out,
                         int t, int last) {
    __shared__ float sWih[96 * 33];
    __shared__ float sWhh[96 * 33];
    __shared__ float sbih[96], sbhh[96], sb2[32], sWo[32];
    __shared__ float racc[4][32];
    __shared__ float rden[4];
    int tid = threadIdx.x;
    for (int j = tid; j < 96 * 32; j += blockDim.x) {
        int r = j >> 5, k = j & 31;
        sWih[r * 33 + k] = Wih[j];
        sWhh[r * 33 + k] = Whh[j];
    }
    for (int j = tid; j < 96; j += blockDim.x) { sbih[j] = bih[j]; sbhh[j] = bhh[j]; }
    for (int j = tid; j < 32; j += blockDim.x) { sb2[j] = b2[j]; sWo[j] = Wout[j]; }
    __syncthreads();

    int warp = tid >> 5, lane = tid & 31;
    int pair = warp >> 1, sub = warp & 1;
    int n = blockIdx.x * 4 + pair;          // 5000 blocks * 4 nodes = 20000 exactly

    float ad2v = g_ad2[n];
    const int* offp = g_off + t * (NN + 1);
    const int* slp  = g_srclist + (size_t)t * ETOT;
    int beg = offp[n], end = offp[n + 1];

    float acc = 0.f, den = 0.f;
    int e = beg + sub;                       // this warp takes every other edge
    // unroll-2: two independent edge chains in flight
    for (; e + 2 < end; e += 4) {
        int s0 = slp[e];
        int s1 = slp[e + 2];
        float a0 = __ldg(&g_as2[s0]);
        float a1 = __ldg(&g_as2[s1]);
        float h0 = g_h2[(size_t)s0 * HID + lane];
        float h1 = g_h2[(size_t)s1 * HID + lane];
        float r0 = a0 + ad2v; r0 = (r0 > 0.f) ? r0 : 0.2f * r0;
        float r1 = a1 + ad2v; r1 = (r1 > 0.f) ? r1 : 0.2f * r1;
        float w0 = __expf(r0);
        float w1 = __expf(r1);
        den += w0 + w1;
        acc += w0 * h0 + w1 * h1;
    }
    for (; e < end; e += 2) {
        int s = slp[e];
        float raw = __ldg(&g_as2[s]) + ad2v;
        raw = (raw > 0.f) ? raw : 0.2f * raw;
        float w = __expf(raw);
        den += w;
        acc += w * g_h2[(size_t)s * HID + lane];
    }

    if (sub == 1) {
        racc[pair][lane] = acc;
        if (lane == 0) rden[pair] = den;
    }
    __syncthreads();
    if (sub == 1) return;
    acc += racc[pair][lane];
    den += rden[pair];

    float o = acc / (den + 1e-16f) + sb2[lane];
    float z2 = (o > 0.f) ? o : (__expf(o) - 1.0f);
    float hv = g_h[(size_t)n * HID + lane];

    float ri = 0.f, zi = 0.f, ni = 0.f, rh = 0.f, zh = 0.f, nh = 0.f;
#pragma unroll
    for (int k = 0; k < 32; k++) {
        float zk = __shfl_sync(0xffffffffu, z2, k);
        float hk = __shfl_sync(0xffffffffu, hv, k);
        ri += zk * sWih[lane * 33 + k];
        zi += zk * sWih[(32 + lane) * 33 + k];
        ni += zk * sWih[(64 + lane) * 33 + k];
        rh += hk * sWhh[lane * 33 + k];
        zh += hk * sWhh[(32 + lane) * 33 + k];
        nh += hk * sWhh[(64 + lane) * 33 + k];
    }
    float r = 1.0f / (1.0f + __expf(-(ri + sbih[lane] + rh + sbhh[lane])));
    float z = 1.0f / (1.0f + __expf(-(zi + sbih[32 + lane] + zh + sbhh[32 + lane])));
    float ng = tanhf(ni + sbih[64 + lane] + r * (nh + sbhh[64 + lane]));
    float hnew = (1.0f - z) * ng + z * hv;
    g_h[(size_t)n * HID + lane] = hnew;

    if (last) {
        float v = hnew * sWo[lane];
#pragma unroll
        for (int o2 = 16; o2; o2 >>= 1) v += __shfl_xor_sync(0xffffffffu, v, o2);
        if (lane == 0) out[n] = v + bout[0];
    }
}

// ---------------- launcher ----------------
extern "C" void kernel_launch(void* const* d_in, const int* in_sizes, int n_in,
                              void* d_out, int out_size) {
    const float* x    = (const float*)d_in[0];
    const int*   ei   = (const int*)  d_in[1];
    const float* W1   = (const float*)d_in[2];
    const float* as1  = (const float*)d_in[3];
    const float* ad1  = (const float*)d_in[4];
    const float* b1   = (const float*)d_in[5];
    const float* W2   = (const float*)d_in[6];
    const float* as2  = (const float*)d_in[7];
    const float* ad2  = (const float*)d_in[8];
    const float* b2   = (const float*)d_in[9];
    const float* Wih  = (const float*)d_in[10];
    const float* Whh  = (const float*)d_in[11];
    const float* bih  = (const float*)d_in[12];
    const float* bhh  = (const float*)d_in[13];
    const float* Wout = (const float*)d_in[14];
    const float* bout = (const float*)d_in[15];
    float* out = (float*)d_out;

    dim3 eg((EE + 255) / 256, TT);

    k_setup<<<160, 256>>>(W1, as1, ad1);
    k_count<<<eg, 256>>>(ei);
    k_scan<<<TT, 1024>>>();
    k_scatter<<<eg, 256>>>(ei);
    for (int t = 0; t < TT; t++) {
        const float* xt = x + (size_t)t * NN;
        k_layer1<<<NN / 8, 256>>>(xt, W1, b1, W2, as2, ad2, t);
        k_layer2<<<NN / 4, 256>>>(b2, Wih, Whh, bih, bhh, Wout, bout, out,
                                  t, (t == TT - 1) ? 1 : 0);
    }
}

// round 5
// speedup vs baseline: 1.7778x; 1.3555x over previous
#include <cuda_runtime.h>
#include <cstdint>

#define TT   8
#define NN   20000
#define EE   640000
#define HID  32
#define CAP  96          // padded slots per (t,node); slot 0 = self-loop. P(overflow) ~ 1e-18

// ---------------- static device scratch ----------------
__device__ int   g_cursor[TT * NN];
__device__ int   g_srclist[(size_t)TT * NN * CAP];
__device__ float g_h2[NN * HID];
__device__ float g_as2[NN];
__device__ float g_ad2[NN];
__device__ float g_h[NN * HID];     // GRU hidden state
__device__ float g_A1[4];           // As1[0..1], Ad1[0..1]

// ---------------- setup: zero h, cursor=1, self-loops, fold layer-1 attn ----------------
__global__ void k_setup(const float* __restrict__ W1,
                        const float* __restrict__ as1,
                        const float* __restrict__ ad1) {
    int i = blockIdx.x * blockDim.x + threadIdx.x;
    int stride = gridDim.x * blockDim.x;
    for (int j = i; j < NN * HID; j += stride) g_h[j] = 0.0f;
    for (int j = i; j < TT * NN; j += stride) {
        g_cursor[j] = 1;
        g_srclist[(size_t)j * CAP] = j % NN;   // self-loop in slot 0
    }
    if (blockIdx.x == 0 && threadIdx.x < 4) {
        int h = threadIdx.x & 1;
        const float* a = (threadIdx.x >= 2) ? ad1 : as1;
        float s = 0.0f;
        for (int c = 0; c < HID; c++) s += W1[h * HID + c] * a[h * HID + c];
        g_A1[threadIdx.x] = s;
    }
}

// ---------------- single-pass scatter into padded rows (2 edges/thread) ----------------
__global__ void k_scatter(const int* __restrict__ ei) {
    int t = blockIdx.y;
    int i = (blockIdx.x * blockDim.x + threadIdx.x) * 2;   // grid sized so i < EE always
    const size_t tb = (size_t)t * 2 * EE;
    int2 src = *(const int2*)&ei[tb + i];
    int2 dst = *(const int2*)&ei[tb + EE + i];
    int cb = t * NN;
    int p0 = atomicAdd(&g_cursor[cb + dst.x], 1);
    g_srclist[((size_t)cb + dst.x) * CAP + p0] = src.x;
    int p1 = atomicAdd(&g_cursor[cb + dst.y], 1);
    g_srclist[((size_t)cb + dst.y) * CAP + p1] = src.y;
}

// ---------------- layer 1: warp-per-node scalar attention + projection ----------------
__global__ void k_layer1(const float* __restrict__ xt,
                         const float* __restrict__ W1,
                         const float* __restrict__ b1,
                         const float* __restrict__ W2,
                         const float* __restrict__ as2w,
                         const float* __restrict__ ad2w,
                         int t) {
    __shared__ float sW1[64], sB1[64], sW2[64 * 32], sAs2[32], sAd2[32];
    int tid = threadIdx.x;
    for (int j = tid; j < 64; j += blockDim.x) { sW1[j] = W1[j]; sB1[j] = b1[j]; }
    for (int j = tid; j < 2048; j += blockDim.x) sW2[j] = W2[j];
    for (int j = tid; j < 32; j += blockDim.x) { sAs2[j] = as2w[j]; sAd2[j] = ad2w[j]; }
    __syncthreads();

    int warp = tid >> 5, lane = tid & 31;
    int n = blockIdx.x * 8 + warp;          // 2500 blocks * 8 warps = 20000 exactly

    float As10 = g_A1[0], As11 = g_A1[1], Ad10 = g_A1[2], Ad11 = g_A1[3];
    float xd = xt[n];
    int deg = g_cursor[t * NN + n];
    const int* slp = g_srclist + ((size_t)t * NN + n) * CAP;

    float den0 = 0.f, den1 = 0.f, num0 = 0.f, num1 = 0.f;
    // pipelined over lane-strided edges
    int e = lane;
    bool v = e < deg;
    int s = v ? slp[e] : 0;
    while (v) {
        int e2 = e + 32;
        bool v2 = e2 < deg;
        int s2 = v2 ? slp[e2] : 0;
        float xs = __ldg(&xt[s]);
        float r0 = xs * As10 + xd * Ad10; r0 = (r0 > 0.f) ? r0 : 0.2f * r0;
        float w0 = __expf(r0); den0 += w0; num0 += w0 * xs;
        float r1 = xs * As11 + xd * Ad11; r1 = (r1 > 0.f) ? r1 : 0.2f * r1;
        float w1 = __expf(r1); den1 += w1; num1 += w1 * xs;
        e = e2; v = v2; s = s2;
    }
#pragma unroll
    for (int o = 16; o; o >>= 1) {
        den0 += __shfl_xor_sync(0xffffffffu, den0, o);
        num0 += __shfl_xor_sync(0xffffffffu, num0, o);
        den1 += __shfl_xor_sync(0xffffffffu, den1, o);
        num1 += __shfl_xor_sync(0xffffffffu, num1, o);
    }
    float S0 = num0 / (den0 + 1e-16f);
    float S1 = num1 / (den1 + 1e-16f);

    float v0 = S0 * sW1[lane] + sB1[lane];
    float z1a = (v0 > 0.f) ? v0 : (__expf(v0) - 1.0f);
    float v1 = S1 * sW1[32 + lane] + sB1[32 + lane];
    float z1b = (v1 > 0.f) ? v1 : (__expf(v1) - 1.0f);

    float a = 0.f;
#pragma unroll
    for (int k = 0; k < 32; k++) {
        float zk = __shfl_sync(0xffffffffu, z1a, k);
        a += zk * sW2[k * 32 + lane];
    }
#pragma unroll
    for (int k = 0; k < 32; k++) {
        float zk = __shfl_sync(0xffffffffu, z1b, k);
        a += zk * sW2[(32 + k) * 32 + lane];
    }
    g_h2[(size_t)n * HID + lane] = a;

    float p = a * sAs2[lane];
    float q = a * sAd2[lane];
#pragma unroll
    for (int o = 16; o; o >>= 1) {
        p += __shfl_xor_sync(0xffffffffu, p, o);
        q += __shfl_xor_sync(0xffffffffu, q, o);
    }
    if (lane == 0) { g_as2[n] = p; g_ad2[n] = q; }
}

// ---------------- layer 2: warp/node, 4 edge-groups x 8 lanes, float4 rows, fused GRU ----------------
__global__ void k_layer2(const float* __restrict__ b2,
                         const float* __restrict__ Wih,
                         const float* __restrict__ Whh,
                         const float* __restrict__ bih,
                         const float* __restrict__ bhh,
                         const float* __restrict__ Wout,
                         const float* __restrict__ bout,
                         float* __restrict__ out,
                         int t, int last) {
    __shared__ float sWih[96 * 33];
    __shared__ float sWhh[96 * 33];
    __shared__ float sbih[96], sbhh[96], sb2[32], sWo[32];
    __shared__ float sred[8][32];
    int tid = threadIdx.x;
    for (int j = tid; j < 96 * 32; j += blockDim.x) {
        int r = j >> 5, k = j & 31;
        sWih[r * 33 + k] = Wih[j];
        sWhh[r * 33 + k] = Whh[j];
    }
    for (int j = tid; j < 96; j += blockDim.x) { sbih[j] = bih[j]; sbhh[j] = bhh[j]; }
    for (int j = tid; j < 32; j += blockDim.x) { sb2[j] = b2[j]; sWo[j] = Wout[j]; }
    __syncthreads();

    int warp = tid >> 5, lane = tid & 31;
    int glane = lane >> 3;          // edge group 0..3
    int clane = lane & 7;           // channel quarter: channels clane*4..clane*4+3
    int n = blockIdx.x * 8 + warp;  // 2500 blocks * 8 warps = 20000 exactly

    float ad2v = g_ad2[n];
    int deg = g_cursor[t * NN + n];
    const int* slp = g_srclist + ((size_t)t * NN + n) * CAP;

    float4 acc = make_float4(0.f, 0.f, 0.f, 0.f);
    float den = 0.f;

    // 2-deep pipelined gather: group g takes edges g, g+4, g+8, ...
    int e0 = glane;
    bool v0 = e0 < deg;
    int s0 = v0 ? slp[e0] : 0;
    float a0 = __ldg(&g_as2[s0]);
    float4 h0 = *(const float4*)&g_h2[(size_t)s0 * HID + (clane << 2)];
    int e1 = e0 + 4;
    bool v1 = e1 < deg;
    int s1 = v1 ? slp[e1] : 0;
    while (v0) {
        // issue next-stage data loads (independent of current consume)
        float a1 = __ldg(&g_as2[s1]);
        float4 h1 = *(const float4*)&g_h2[(size_t)s1 * HID + (clane << 2)];
        // prefetch src index two stages ahead
        int e2 = e1 + 4;
        bool v2 = e2 < deg;
        int s2 = v2 ? slp[e2] : 0;
        // consume current
        float r = a0 + ad2v; r = (r > 0.f) ? r : 0.2f * r;
        float w = __expf(r);
        den += w;
        acc.x += w * h0.x; acc.y += w * h0.y; acc.z += w * h0.z; acc.w += w * h0.w;
        a0 = a1; h0 = h1; v0 = v1;
        s1 = s2; v1 = v2; e1 = e2;
    }

    // reduce across the 4 groups (flip lane bits 3 and 4)
#pragma unroll
    for (int o = 8; o <= 16; o <<= 1) {
        acc.x += __shfl_xor_sync(0xffffffffu, acc.x, o);
        acc.y += __shfl_xor_sync(0xffffffffu, acc.y, o);
        acc.z += __shfl_xor_sync(0xffffffffu, acc.z, o);
        acc.w += __shfl_xor_sync(0xffffffffu, acc.w, o);
        den   += __shfl_xor_sync(0xffffffffu, den, o);
    }
    // redistribute: lane c must hold channel c
    if (glane == 0) *(float4*)&sred[warp][clane << 2] = acc;
    __syncwarp();
    float o = sred[warp][lane] / (den + 1e-16f) + sb2[lane];
    float z2 = (o > 0.f) ? o : (__expf(o) - 1.0f);
    float hv = g_h[(size_t)n * HID + lane];

    float ri = 0.f, zi = 0.f, ni = 0.f, rh = 0.f, zh = 0.f, nh = 0.f;
#pragma unroll
    for (int k = 0; k < 32; k++) {
        float zk = __shfl_sync(0xffffffffu, z2, k);
        float hk = __shfl_sync(0xffffffffu, hv, k);
        ri += zk * sWih[lane * 33 + k];
        zi += zk * sWih[(32 + lane) * 33 + k];
        ni += zk * sWih[(64 + lane) * 33 + k];
        rh += hk * sWhh[lane * 33 + k];
        zh += hk * sWhh[(32 + lane) * 33 + k];
        nh += hk * sWhh[(64 + lane) * 33 + k];
    }
    float r = 1.0f / (1.0f + __expf(-(ri + sbih[lane] + rh + sbhh[lane])));
    float z = 1.0f / (1.0f + __expf(-(zi + sbih[32 + lane] + zh + sbhh[32 + lane])));
    float ng = tanhf(ni + sbih[64 + lane] + r * (nh + sbhh[64 + lane]));
    float hnew = (1.0f - z) * ng + z * hv;
    g_h[(size_t)n * HID + lane] = hnew;

    if (last) {
        float vv = hnew * sWo[lane];
#pragma unroll
        for (int o2 = 16; o2; o2 >>= 1) vv += __shfl_xor_sync(0xffffffffu, vv, o2);
        if (lane == 0) out[n] = vv + bout[0];
    }
}

// ---------------- launcher ----------------
extern "C" void kernel_launch(void* const* d_in, const int* in_sizes, int n_in,
                              void* d_out, int out_size) {
    const float* x    = (const float*)d_in[0];
    const int*   ei   = (const int*)  d_in[1];
    const float* W1   = (const float*)d_in[2];
    const float* as1  = (const float*)d_in[3];
    const float* ad1  = (const float*)d_in[4];
    const float* b1   = (const float*)d_in[5];
    const float* W2   = (const float*)d_in[6];
    const float* as2  = (const float*)d_in[7];
    const float* ad2  = (const float*)d_in[8];
    const float* b2   = (const float*)d_in[9];
    const float* Wih  = (const float*)d_in[10];
    const float* Whh  = (const float*)d_in[11];
    const float* bih  = (const float*)d_in[12];
    const float* bhh  = (const float*)d_in[13];
    const float* Wout = (const float*)d_in[14];
    const float* bout = (const float*)d_in[15];
    float* out = (float*)d_out;

    dim3 sg(EE / 512, TT);   // 2 edges per thread, 256 threads/block

    k_setup<<<160, 256>>>(W1, as1, ad1);
    k_scatter<<<sg, 256>>>(ei);
    for (int t = 0; t < TT; t++) {
        const float* xt = x + (size_t)t * NN;
        k_layer1<<<NN / 8, 256>>>(xt, W1, b1, W2, as2, ad2, t);
        k_layer2<<<NN / 8, 256>>>(b2, Wih, Whh, bih, bhh, Wout, bout, out,
                                  t, (t == TT - 1) ? 1 : 0);
    }
}

// round 6
// speedup vs baseline: 1.8226x; 1.0252x over previous
#include <cuda_runtime.h>
#include <cstdint>

#define TT   8
#define NN   20000
#define EE   640000
#define HID  32
#define CAP  96          // padded slots per (t,node); slot 0 = self-loop. P(overflow) ~ 1e-18
#define L2BLK 2500       // blocks per layer role (8 warps/block * 2500 = 20000 nodes)

// ---------------- static device scratch ----------------
__device__ int   g_cursor[TT * NN];
__device__ int   g_srclist[(size_t)TT * NN * CAP];
__device__ float g_h2[2][NN * HID];     // double buffer (layer1 t+1 overlaps layer2 t)
__device__ float g_as2[2][NN];
__device__ float g_ad2[2][NN];
__device__ float g_h[NN * HID];         // GRU hidden state
__device__ float g_A1[4];               // As1[0..1], Ad1[0..1]

// ---------------- shared-memory layouts ----------------
struct L1S {
    float  W1[64], B1[64];
    float4 W2T[32][17];      // W2T[c][k4] = W2[4k4..4k4+3][c], pitch 17 -> conflict-free
    float  As2[32], Ad2[32];
    float  z1[8][64];        // per-warp staging of z1 vector
};
struct L2S {
    float4 Wih[96][9];       // Wih[row][k4] = W_ih[row][4k4..4k4+3], pitch 9 -> conflict-free
    float4 Whh[96][9];
    float  bih[96], bhh[96], b2[32], Wo[32];
    float  zz[8][32], hh[8][32], red[8][32];
};

// ---------------- setup: zero h, cursor=1, self-loops, fold layer-1 attn ----------------
__global__ void k_setup(const float* __restrict__ W1,
                        const float* __restrict__ as1,
                        const float* __restrict__ ad1) {
    int i = blockIdx.x * blockDim.x + threadIdx.x;
    int stride = gridDim.x * blockDim.x;
    for (int j = i; j < NN * HID; j += stride) g_h[j] = 0.0f;
    for (int j = i; j < TT * NN; j += stride) {
        g_cursor[j] = 1;
        g_srclist[(size_t)j * CAP] = j % NN;   // self-loop in slot 0
    }
    if (blockIdx.x == 0 && threadIdx.x < 4) {
        int h = threadIdx.x & 1;
        const float* a = (threadIdx.x >= 2) ? ad1 : as1;
        float s = 0.0f;
        for (int c = 0; c < HID; c++) s += W1[h * HID + c] * a[h * HID + c];
        g_A1[threadIdx.x] = s;
    }
}

// ---------------- single-pass scatter into padded rows (2 edges/thread) ----------------
__global__ void k_scatter(const int* __restrict__ ei) {
    int t = blockIdx.y;
    int i = (blockIdx.x * blockDim.x + threadIdx.x) * 2;
    const size_t tb = (size_t)t * 2 * EE;
    int2 src = *(const int2*)&ei[tb + i];
    int2 dst = *(const int2*)&ei[tb + EE + i];
    int cb = t * NN;
    int p0 = atomicAdd(&g_cursor[cb + dst.x], 1);
    g_srclist[((size_t)cb + dst.x) * CAP + p0] = src.x;
    int p1 = atomicAdd(&g_cursor[cb + dst.y], 1);
    g_srclist[((size_t)cb + dst.y) * CAP + p1] = src.y;
}

// ---------------- layer 1 body: warp-per-node scalar attention + float4 projection ----------------
__device__ __forceinline__ void layer1_body(
        L1S* s, int bid,
        const float* __restrict__ xt,
        const float* __restrict__ W1, const float* __restrict__ b1,
        const float* __restrict__ W2,
        const float* __restrict__ as2w, const float* __restrict__ ad2w,
        int t) {
    int tid = threadIdx.x;
    for (int j = tid; j < 64; j += 256) { s->W1[j] = W1[j]; s->B1[j] = b1[j]; }
    for (int j = tid; j < 512; j += 256) {
        int c = j >> 4, k4 = j & 15;
        s->W2T[c][k4] = make_float4(W2[(4 * k4 + 0) * 32 + c], W2[(4 * k4 + 1) * 32 + c],
                                    W2[(4 * k4 + 2) * 32 + c], W2[(4 * k4 + 3) * 32 + c]);
    }
    for (int j = tid; j < 32; j += 256) { s->As2[j] = as2w[j]; s->Ad2[j] = ad2w[j]; }
    __syncthreads();

    int warp = tid >> 5, lane = tid & 31;
    int n = bid * 8 + warp;

    float As10 = g_A1[0], As11 = g_A1[1], Ad10 = g_A1[2], Ad11 = g_A1[3];
    float xd = xt[n];
    int deg = g_cursor[t * NN + n];
    const int* slp = g_srclist + ((size_t)t * NN + n) * CAP;

    float den0 = 0.f, den1 = 0.f, num0 = 0.f, num1 = 0.f;
    int e = lane;
    bool v = e < deg;
    int sidx = v ? slp[e] : 0;
    while (v) {
        int e2 = e + 32;
        bool v2 = e2 < deg;
        int s2 = v2 ? slp[e2] : 0;
        float xs = __ldg(&xt[sidx]);
        float r0 = xs * As10 + xd * Ad10; r0 = (r0 > 0.f) ? r0 : 0.2f * r0;
        float w0 = __expf(r0); den0 += w0; num0 += w0 * xs;
        float r1 = xs * As11 + xd * Ad11; r1 = (r1 > 0.f) ? r1 : 0.2f * r1;
        float w1 = __expf(r1); den1 += w1; num1 += w1 * xs;
        e = e2; v = v2; sidx = s2;
    }
#pragma unroll
    for (int o = 16; o; o >>= 1) {
        den0 += __shfl_xor_sync(0xffffffffu, den0, o);
        num0 += __shfl_xor_sync(0xffffffffu, num0, o);
        den1 += __shfl_xor_sync(0xffffffffu, den1, o);
        num1 += __shfl_xor_sync(0xffffffffu, num1, o);
    }
    float S0 = num0 / (den0 + 1e-16f);
    float S1 = num1 / (den1 + 1e-16f);

    float v0 = S0 * s->W1[lane] + s->B1[lane];
    float z1a = (v0 > 0.f) ? v0 : (__expf(v0) - 1.0f);
    float v1 = S1 * s->W1[32 + lane] + s->B1[32 + lane];
    float z1b = (v1 > 0.f) ? v1 : (__expf(v1) - 1.0f);

    s->z1[warp][lane] = z1a;
    s->z1[warp][32 + lane] = z1b;
    __syncwarp();

    // a[c=lane] = sum_k z1[k] * W2[k][c], float4 over k
    float a = 0.f;
#pragma unroll
    for (int k4 = 0; k4 < 16; k4++) {
        float4 z4 = *(const float4*)&s->z1[warp][k4 * 4];   // broadcast
        float4 w4 = s->W2T[lane][k4];
        a += z4.x * w4.x + z4.y * w4.y + z4.z * w4.z + z4.w * w4.w;
    }
    int buf = t & 1;
    g_h2[buf][(size_t)n * HID + lane] = a;

    float p = a * s->As2[lane];
    float q = a * s->Ad2[lane];
#pragma unroll
    for (int o = 16; o; o >>= 1) {
        p += __shfl_xor_sync(0xffffffffu, p, o);
        q += __shfl_xor_sync(0xffffffffu, q, o);
    }
    if (lane == 0) { g_as2[buf][n] = p; g_ad2[buf][n] = q; }
}

// ---------------- layer 2 body: gather + float4 GRU (+ fused output at last step) ----------------
__device__ __forceinline__ void layer2_body(
        L2S* s, int bid,
        const float* __restrict__ b2,
        const float* __restrict__ Wih, const float* __restrict__ Whh,
        const float* __restrict__ bih, const float* __restrict__ bhh,
        const float* __restrict__ Wout, const float* __restrict__ bout,
        float* __restrict__ out, int t, int last) {
    int tid = threadIdx.x;
    for (int j = tid; j < 96 * 8; j += 256) {
        int r = j >> 3, k4 = j & 7;
        s->Wih[r][k4] = ((const float4*)Wih)[r * 8 + k4];
        s->Whh[r][k4] = ((const float4*)Whh)[r * 8 + k4];
    }
    for (int j = tid; j < 96; j += 256) { s->bih[j] = bih[j]; s->bhh[j] = bhh[j]; }
    for (int j = tid; j < 32; j += 256) { s->b2[j] = b2[j]; s->Wo[j] = Wout[j]; }
    __syncthreads();

    int warp = tid >> 5, lane = tid & 31;
    int glane = lane >> 3;          // edge group 0..3
    int clane = lane & 7;           // channel quarter
    int n = bid * 8 + warp;

    int buf = t & 1;
    const float* as2p = g_as2[buf];
    const float* h2p  = g_h2[buf];
    float ad2v = g_ad2[buf][n];
    int deg = g_cursor[t * NN + n];
    const int* slp = g_srclist + ((size_t)t * NN + n) * CAP;

    float4 acc = make_float4(0.f, 0.f, 0.f, 0.f);
    float den = 0.f;

    int e0 = glane;
    bool v0 = e0 < deg;
    int s0 = v0 ? slp[e0] : 0;
    float a0 = __ldg(&as2p[s0]);
    float4 h0 = *(const float4*)&h2p[(size_t)s0 * HID + (clane << 2)];
    int e1 = e0 + 4;
    bool v1 = e1 < deg;
    int s1 = v1 ? slp[e1] : 0;
    while (v0) {
        float a1 = __ldg(&as2p[s1]);
        float4 h1 = *(const float4*)&h2p[(size_t)s1 * HID + (clane << 2)];
        int e2 = e1 + 4;
        bool v2 = e2 < deg;
        int s2 = v2 ? slp[e2] : 0;
        float r = a0 + ad2v; r = (r > 0.f) ? r : 0.2f * r;
        float w = __expf(r);
        den += w;
        acc.x += w * h0.x; acc.y += w * h0.y; acc.z += w * h0.z; acc.w += w * h0.w;
        a0 = a1; h0 = h1; v0 = v1;
        s1 = s2; v1 = v2; e1 = e2;
    }

#pragma unroll
    for (int o = 8; o <= 16; o <<= 1) {
        acc.x += __shfl_xor_sync(0xffffffffu, acc.x, o);
        acc.y += __shfl_xor_sync(0xffffffffu, acc.y, o);
        acc.z += __shfl_xor_sync(0xffffffffu, acc.z, o);
        acc.w += __shfl_xor_sync(0xffffffffu, acc.w, o);
        den   += __shfl_xor_sync(0xffffffffu, den, o);
    }
    if (glane == 0) *(float4*)&s->red[warp][clane << 2] = acc;
    __syncwarp();
    float o = s->red[warp][lane] / (den + 1e-16f) + s->b2[lane];
    float z2 = (o > 0.f) ? o : (__expf(o) - 1.0f);
    float hv = g_h[(size_t)n * HID + lane];

    s->zz[warp][lane] = z2;
    s->hh[warp][lane] = hv;
    __syncwarp();

    float ri = 0.f, zi = 0.f, ni = 0.f, rh = 0.f, zh = 0.f, nh = 0.f;
#pragma unroll
    for (int k4 = 0; k4 < 8; k4++) {
        float4 z4 = *(const float4*)&s->zz[warp][k4 * 4];   // broadcast
        float4 h4 = *(const float4*)&s->hh[warp][k4 * 4];   // broadcast
        float4 wr = s->Wih[lane][k4];
        float4 wz = s->Wih[32 + lane][k4];
        float4 wn = s->Wih[64 + lane][k4];
        float4 ur = s->Whh[lane][k4];
        float4 uz = s->Whh[32 + lane][k4];
        float4 un = s->Whh[64 + lane][k4];
        ri += z4.x * wr.x + z4.y * wr.y + z4.z * wr.z + z4.w * wr.w;
        zi += z4.x * wz.x + z4.y * wz.y + z4.z * wz.z + z4.w * wz.w;
        ni += z4.x * wn.x + z4.y * wn.y + z4.z * wn.z + z4.w * wn.w;
        rh += h4.x * ur.x + h4.y * ur.y + h4.z * ur.z + h4.w * ur.w;
        zh += h4.x * uz.x + h4.y * uz.y + h4.z * uz.z + h4.w * uz.w;
        nh += h4.x * un.x + h4.y * un.y + h4.z * un.z + h4.w * un.w;
    }
    float r = 1.0f / (1.0f + __expf(-(ri + s->bih[lane] + rh + s->bhh[lane])));
    float z = 1.0f / (1.0f + __expf(-(zi + s->bih[32 + lane] + zh + s->bhh[32 + lane])));
    float ng = tanhf(ni + s->bih[64 + lane] + r * (nh + s->bhh[64 + lane]));
    float hnew = (1.0f - z) * ng + z * hv;
    g_h[(size_t)n * HID + lane] = hnew;

    if (last) {
        float vv = hnew * s->Wo[lane];
#pragma unroll
        for (int o2 = 16; o2; o2 >>= 1) vv += __shfl_xor_sync(0xffffffffu, vv, o2);
        if (lane == 0) out[n] = vv + bout[0];
    }
}

// ---------------- kernels ----------------
__global__ void __launch_bounds__(256) k_l1first(
        const float* xt, const float* W1, const float* b1, const float* W2,
        const float* as2w, const float* ad2w) {
    __shared__ L1S sm;
    layer1_body(&sm, blockIdx.x, xt, W1, b1, W2, as2w, ad2w, 0);
}

// blocks [0, L2BLK): layer2 at t.  blocks [L2BLK, 2*L2BLK): layer1 at t+1.
__global__ void __launch_bounds__(256) k_fused(
        const float* xnext,
        const float* W1, const float* b1, const float* W2,
        const float* as2w, const float* ad2w,
        const float* b2, const float* Wih, const float* Whh,
        const float* bih, const float* bhh,
        const float* Wout, const float* bout,
        float* out, int t, int last) {
    __shared__ union { L1S l1; L2S l2; } sm;
    if ((int)blockIdx.x < L2BLK) {
        layer2_body(&sm.l2, blockIdx.x, b2, Wih, Whh, bih, bhh, Wout, bout,
                    out, t, last);
    } else {
        layer1_body(&sm.l1, blockIdx.x - L2BLK, xnext, W1, b1, W2, as2w, ad2w, t + 1);
    }
}

// ---------------- launcher ----------------
extern "C" void kernel_launch(void* const* d_in, const int* in_sizes, int n_in,
                              void* d_out, int out_size) {
    const float* x    = (const float*)d_in[0];
    const int*   ei   = (const int*)  d_in[1];
    const float* W1   = (const float*)d_in[2];
    const float* as1  = (const float*)d_in[3];
    const float* ad1  = (const float*)d_in[4];
    const float* b1   = (const float*)d_in[5];
    const float* W2   = (const float*)d_in[6];
    const float* as2  = (const float*)d_in[7];
    const float* ad2  = (const float*)d_in[8];
    const float* b2   = (const float*)d_in[9];
    const float* Wih  = (const float*)d_in[10];
    const float* Whh  = (const float*)d_in[11];
    const float* bih  = (const float*)d_in[12];
    const float* bhh  = (const float*)d_in[13];
    const float* Wout = (const float*)d_in[14];
    const float* bout = (const float*)d_in[15];
    float* out = (float*)d_out;

    dim3 sg(EE / 512, TT);   // 2 edges per thread, 256 threads/block

    k_setup<<<160, 256>>>(W1, as1, ad1);
    k_scatter<<<sg, 256>>>(ei);
    k_l1first<<<L2BLK, 256>>>(x, W1, b1, W2, as2, ad2);
    for (int t = 0; t < TT - 1; t++) {
        const float* xnext = x + (size_t)(t + 1) * NN;
        k_fused<<<2 * L2BLK, 256>>>(xnext, W1, b1, W2, as2, ad2,
                                    b2, Wih, Whh, bih, bhh, Wout, bout,
                                    out, t, 0);
    }
    // last step: layer2 only
    k_fused<<<L2BLK, 256>>>(x, W1, b1, W2, as2, ad2,
                            b2, Wih, Whh, bih, bhh, Wout, bout,
                            out, TT - 1, 1);
}